// round 9
// baseline (speedup 1.0000x reference)
#include <cuda_runtime.h>
#include <cuda_fp16.h>
#include <cstdint>

#define NUM_USERS 100000
#define NUM_ITEMS 50000
#define EMB_DIM   64
#define N_NODES   (NUM_USERS + NUM_ITEMS)   // 150000
#define N_EDGES   4000000
#define BATCH     4096
#define NFLOAT    (N_NODES * EMB_DIM)        // 9,600,000
#define NV4       (NFLOAT / 4)               // 2,400,000

#define SCAN_BLK  1024
#define SCAN_NB   ((N_NODES + SCAN_BLK - 1) / SCAN_BLK)   // 147

// Device-global scratch (no runtime allocation allowed)
__device__ float  g_x1[NFLOAT];              // fp32 layer outputs (score path)
__device__ float  g_x2[NFLOAT];
__device__ float  g_x3[NFLOAT];
__device__ __half g_h0[NFLOAT];              // fp16 gather operand, layer 1
__device__ __half g_h1[NFLOAT];              // fp16 gather operand, layer 2
__device__ int    g_deg[N_NODES];
__device__ int    g_start[N_NODES];
__device__ int    g_fill[N_NODES];
__device__ int    g_bsum[256];
__device__ int    g_boff[256];
__device__ int    g_list[3 * BATCH];         // rows needed from layer 3
__device__ int2   g_epack[N_EDGES];          // (col, val-bits) grouped by row

// ---------------------------------------------------------------------------
// Prep: zero degree counters + build the layer-3 row list (fixed slots, dups ok)
// ---------------------------------------------------------------------------
__global__ void prep_kernel(const int* __restrict__ users,
                            const int* __restrict__ pos_items,
                            const int* __restrict__ neg_items) {
    int i = blockIdx.x * blockDim.x + threadIdx.x;
    if (i < N_NODES) g_deg[i] = 0;
    if (i < BATCH) {
        g_list[i]             = users[i];
        g_list[BATCH + i]     = NUM_USERS + pos_items[i];
        g_list[2 * BATCH + i] = NUM_USERS + neg_items[i];
    }
}

// ---------------------------------------------------------------------------
// x0 -> fp16 shadow (concat semantics)
// ---------------------------------------------------------------------------
__global__ void tohalf_kernel(const float* __restrict__ user_emb,
                              const float* __restrict__ item_emb) {
    int i = blockIdx.x * blockDim.x + threadIdx.x;   // float4 index
    if (i >= NV4) return;
    int node = i >> 4;
    float4 v = (node < NUM_USERS)
        ? ((const float4*)user_emb)[i]
        : ((const float4*)item_emb)[i - NUM_USERS * (EMB_DIM / 4)];
    __half2 h0 = __floats2half2_rn(v.x, v.y);
    __half2 h1 = __floats2half2_rn(v.z, v.w);
    ((__half2*)g_h0)[2 * i]     = h0;
    ((__half2*)g_h0)[2 * i + 1] = h1;
}

// ---------------------------------------------------------------------------
// CSR build: histogram -> block scan (3 kernels) -> packed scatter
// ---------------------------------------------------------------------------
__global__ void hist_kernel(const int* __restrict__ row) {
    int i = blockIdx.x * blockDim.x + threadIdx.x;
    if (i < N_EDGES) atomicAdd(&g_deg[row[i]], 1);
}

__global__ void scan1_kernel() {                     // per-block exclusive scan
    __shared__ int sm[SCAN_BLK];
    int tid = threadIdx.x;
    int i = blockIdx.x * SCAN_BLK + tid;
    int d = (i < N_NODES) ? g_deg[i] : 0;
    sm[tid] = d;
    __syncthreads();
    #pragma unroll
    for (int off = 1; off < SCAN_BLK; off <<= 1) {
        int t = (tid >= off) ? sm[tid - off] : 0;
        __syncthreads();
        sm[tid] += t;
        __syncthreads();
    }
    if (i < N_NODES) g_start[i] = sm[tid] - d;       // exclusive
    if (tid == SCAN_BLK - 1) g_bsum[blockIdx.x] = sm[tid];
}

__global__ void scan2_kernel() {                     // scan the 147 block sums
    __shared__ int sm[256];
    int tid = threadIdx.x;
    int d = (tid < SCAN_NB) ? g_bsum[tid] : 0;
    sm[tid] = d;
    __syncthreads();
    #pragma unroll
    for (int off = 1; off < 256; off <<= 1) {
        int t = (tid >= off) ? sm[tid - off] : 0;
        __syncthreads();
        sm[tid] += t;
        __syncthreads();
    }
    if (tid < SCAN_NB) g_boff[tid] = sm[tid] - d;    // exclusive
}

__global__ void scan3_kernel() {                     // add block offsets
    int i = blockIdx.x * SCAN_BLK + threadIdx.x;
    if (i < N_NODES) {
        int s = g_start[i] + g_boff[blockIdx.x];
        g_start[i] = s;
        g_fill[i]  = s;
    }
}

__global__ void scatter_kernel(const int* __restrict__ row,
                               const int* __restrict__ col,
                               const float* __restrict__ vals) {
    int i = blockIdx.x * blockDim.x + threadIdx.x;
    if (i >= N_EDGES) return;
    int p = atomicAdd(&g_fill[row[i]], 1);
    g_epack[p] = make_int2(col[i], __float_as_int(vals[i]));
}

// ---------------------------------------------------------------------------
// Pull-mode CSR SpMM, fp16 gather operand, fp32 accumulate.
//   y[r] = sum_{k in row r} val_k * xh[col_k]
// One warp per row; lane owns 2 dims (half2 load = 128 B/row coalesced).
// WRITE_HALF: also emit fp16 shadow for the next layer.
// ---------------------------------------------------------------------------
template<bool WRITE_HALF>
__global__ void __launch_bounds__(256)
spmm_csr_kernel(const __half2* __restrict__ xh,
                float* __restrict__ y,
                __half* __restrict__ yh) {
    const unsigned FULL = 0xFFFFFFFFu;
    int r    = (blockIdx.x * blockDim.x + threadIdx.x) >> 5;
    int lane = threadIdx.x & 31;
    if (r >= N_NODES) return;

    int start = g_start[r];
    int deg   = g_deg[r];

    float ax = 0.f, ay = 0.f;

    int k = 0;
    for (; k + 32 <= deg; k += 32) {
        int2 pk = g_epack[start + k + lane];
        #pragma unroll 8
        for (int j = 0; j < 32; j++) {
            int   cc = __shfl_sync(FULL, pk.x, j);
            float vv = __int_as_float(__shfl_sync(FULL, pk.y, j));
            float2 xv = __half22float2(xh[(size_t)cc * 32 + lane]);
            ax += vv * xv.x;
            ay += vv * xv.y;
        }
    }
    int n = deg - k;
    if (n > 0) {
        int2 pk = (lane < n) ? g_epack[start + k + lane] : make_int2(0, 0);
        for (int j = 0; j < n; j++) {
            int   cc = __shfl_sync(FULL, pk.x, j);
            float vv = __int_as_float(__shfl_sync(FULL, pk.y, j));
            float2 xv = __half22float2(xh[(size_t)cc * 32 + lane]);
            ax += vv * xv.x;
            ay += vv * xv.y;
        }
    }

    ((float2*)y)[(size_t)r * 32 + lane] = make_float2(ax, ay);
    if (WRITE_HALF) {
        ((__half2*)yh)[(size_t)r * 32 + lane] = __floats2half2_rn(ax, ay);
    }
}

// ---------------------------------------------------------------------------
// Masked layer-3 SpMM: rows from g_list (only scored rows, ~12K warps),
// gathers fp32 x2 directly (no fp16 shadow needed for this layer).
// ---------------------------------------------------------------------------
__global__ void __launch_bounds__(256)
spmm_csr_masked_kernel(const float* __restrict__ x,
                       float* __restrict__ y) {
    const unsigned FULL = 0xFFFFFFFFu;
    int w    = (blockIdx.x * blockDim.x + threadIdx.x) >> 5;
    int lane = threadIdx.x & 31;
    if (w >= 3 * BATCH) return;
    int r = g_list[w];

    int start = g_start[r];
    int deg   = g_deg[r];

    float ax = 0.f, ay = 0.f;

    int k = 0;
    for (; k + 32 <= deg; k += 32) {
        int2 pk = g_epack[start + k + lane];
        #pragma unroll 8
        for (int j = 0; j < 32; j++) {
            int   cc = __shfl_sync(FULL, pk.x, j);
            float vv = __int_as_float(__shfl_sync(FULL, pk.y, j));
            float2 xv = ((const float2*)x)[(size_t)cc * 32 + lane];
            ax += vv * xv.x;
            ay += vv * xv.y;
        }
    }
    int n = deg - k;
    if (n > 0) {
        int2 pk = (lane < n) ? g_epack[start + k + lane] : make_int2(0, 0);
        for (int j = 0; j < n; j++) {
            int   cc = __shfl_sync(FULL, pk.x, j);
            float vv = __int_as_float(__shfl_sync(FULL, pk.y, j));
            float2 xv = ((const float2*)x)[(size_t)cc * 32 + lane];
            ax += vv * xv.x;
            ay += vv * xv.y;
        }
    }

    ((float2*)y)[(size_t)r * 32 + lane] = make_float2(ax, ay);
}

// ---------------------------------------------------------------------------
// Scoring: one warp per batch element.
// acc = x0 + x1 + x2 + x3 (x0 from fp32 input tables); score = dot/16
// out layout: [pos_scores(4096) | neg_scores(4096)]
// ---------------------------------------------------------------------------
__global__ void score_kernel(const float* __restrict__ user_emb,
                             const float* __restrict__ item_emb,
                             const int* __restrict__ users,
                             const int* __restrict__ pos_items,
                             const int* __restrict__ neg_items,
                             float* __restrict__ out) {
    int warp = (blockIdx.x * blockDim.x + threadIdx.x) >> 5;
    int lane = threadIdx.x & 31;
    if (warp >= BATCH) return;

    int u  = users[warp];
    int pi = pos_items[warp];
    int ni = neg_items[warp];

    const float2* UE = (const float2*)user_emb;
    const float2* IE = (const float2*)item_emb;
    const float2* X1 = (const float2*)g_x1;
    const float2* X2 = (const float2*)g_x2;
    const float2* X3 = (const float2*)g_x3;

    size_t un = (size_t)u * 32 + lane;
    size_t pn = (size_t)(NUM_USERS + pi) * 32 + lane;
    size_t nn = (size_t)(NUM_USERS + ni) * 32 + lane;
    size_t pl = (size_t)pi * 32 + lane;
    size_t nl = (size_t)ni * 32 + lane;

    float2 a, t;
    a = UE[un];
    t = X1[un]; a.x += t.x; a.y += t.y;
    t = X2[un]; a.x += t.x; a.y += t.y;
    t = X3[un]; a.x += t.x; a.y += t.y;
    float2 uacc = a;
    a = IE[pl];
    t = X1[pn]; a.x += t.x; a.y += t.y;
    t = X2[pn]; a.x += t.x; a.y += t.y;
    t = X3[pn]; a.x += t.x; a.y += t.y;
    float2 pacc = a;
    a = IE[nl];
    t = X1[nn]; a.x += t.x; a.y += t.y;
    t = X2[nn]; a.x += t.x; a.y += t.y;
    t = X3[nn]; a.x += t.x; a.y += t.y;
    float2 nacc = a;

    float ps = uacc.x * pacc.x + uacc.y * pacc.y;
    float ns = uacc.x * nacc.x + uacc.y * nacc.y;
    #pragma unroll
    for (int o = 16; o > 0; o >>= 1) {
        ps += __shfl_down_sync(0xFFFFFFFFu, ps, o);
        ns += __shfl_down_sync(0xFFFFFFFFu, ns, o);
    }
    if (lane == 0) {
        out[warp]         = ps * (1.0f / 16.0f);
        out[BATCH + warp] = ns * (1.0f / 16.0f);
    }
}

// ---------------------------------------------------------------------------
extern "C" void kernel_launch(void* const* d_in, const int* in_sizes, int n_in,
                              void* d_out, int out_size) {
    const float* user_emb  = (const float*)d_in[0];
    const float* item_emb  = (const float*)d_in[1];
    const float* vals      = (const float*)d_in[2];
    const int*   row       = (const int*)d_in[3];
    const int*   col       = (const int*)d_in[4];
    const int*   users     = (const int*)d_in[5];
    const int*   pos_items = (const int*)d_in[6];
    const int*   neg_items = (const int*)d_in[7];
    float* out = (float*)d_out;

    float*  x1P; cudaGetSymbolAddress((void**)&x1P, g_x1);
    float*  x2P; cudaGetSymbolAddress((void**)&x2P, g_x2);
    float*  x3P; cudaGetSymbolAddress((void**)&x3P, g_x3);
    __half* h0P; cudaGetSymbolAddress((void**)&h0P, g_h0);
    __half* h1P; cudaGetSymbolAddress((void**)&h1P, g_h1);

    const int TB = 256;
    const int edgeBlocks     = (N_EDGES + TB - 1) / TB;
    const int rowWarpBlocks  = (N_NODES * 32 + TB - 1) / TB;    // warp per row
    const int maskWarpBlocks = (3 * BATCH * 32) / TB;           // 1536 blocks

    prep_kernel<<<(N_NODES + TB - 1) / TB, TB>>>(users, pos_items, neg_items);
    tohalf_kernel<<<(NV4 + TB - 1) / TB, TB>>>(user_emb, item_emb);

    // CSR build
    hist_kernel<<<edgeBlocks, TB>>>(row);
    scan1_kernel<<<SCAN_NB, SCAN_BLK>>>();
    scan2_kernel<<<1, 256>>>();
    scan3_kernel<<<SCAN_NB, SCAN_BLK>>>();
    scatter_kernel<<<edgeBlocks, TB>>>(row, col, vals);

    // Layer 1: h0 -> x1 (+h1)
    spmm_csr_kernel<true><<<rowWarpBlocks, TB>>>((const __half2*)h0P, x1P, h1P);
    // Layer 2: h1 -> x2 (fp32 only; layer 3 gathers fp32)
    spmm_csr_kernel<false><<<rowWarpBlocks, TB>>>((const __half2*)h1P, x2P,
                                                  nullptr);
    // Layer 3 (masked): x2 (fp32) -> x3, only rows consumed by scoring
    spmm_csr_masked_kernel<<<maskWarpBlocks, TB>>>(x2P, x3P);

    score_kernel<<<(BATCH * 32) / TB, TB>>>(user_emb, item_emb,
                                            users, pos_items, neg_items, out);
}

// round 10
// speedup vs baseline: 1.0134x; 1.0134x over previous
#include <cuda_runtime.h>
#include <cuda_fp16.h>
#include <cstdint>

#define NUM_USERS 100000
#define NUM_ITEMS 50000
#define EMB_DIM   64
#define N_NODES   (NUM_USERS + NUM_ITEMS)   // 150000
#define N_EDGES   4000000
#define BATCH     4096
#define NFLOAT    (N_NODES * EMB_DIM)        // 9,600,000
#define NV4       (NFLOAT / 4)               // 2,400,000

#define SCAN_BLK  1024
#define SCAN_NB   ((N_NODES + SCAN_BLK - 1) / SCAN_BLK)   // 147

// Device-global scratch (no runtime allocation allowed)
__device__ float  g_x1[NFLOAT];              // fp32 layer outputs (score path)
__device__ float  g_x2[NFLOAT];
__device__ float  g_x3[NFLOAT];
__device__ __half g_h0[NFLOAT];              // fp16 gather operand, layer 1
__device__ __half g_h1[NFLOAT];              // fp16 gather operand, layer 2
__device__ int    g_deg[N_NODES];
__device__ int    g_start[N_NODES];
__device__ int    g_fill[N_NODES];
__device__ int    g_bsum[256];
__device__ int    g_boff[256];
__device__ int    g_list[3 * BATCH];         // rows needed from layer 3
__device__ int2   g_epack[N_EDGES];          // (col, val-bits) grouped by row

// ---------------------------------------------------------------------------
// Prep: zero degree counters + build the layer-3 row list (fixed slots, dups ok)
// ---------------------------------------------------------------------------
__global__ void prep_kernel(const int* __restrict__ users,
                            const int* __restrict__ pos_items,
                            const int* __restrict__ neg_items) {
    int i = blockIdx.x * blockDim.x + threadIdx.x;
    if (i < N_NODES) g_deg[i] = 0;
    if (i < BATCH) {
        g_list[i]             = users[i];
        g_list[BATCH + i]     = NUM_USERS + pos_items[i];
        g_list[2 * BATCH + i] = NUM_USERS + neg_items[i];
    }
}

// ---------------------------------------------------------------------------
// x0 -> fp16 shadow (concat semantics)
// ---------------------------------------------------------------------------
__global__ void tohalf_kernel(const float* __restrict__ user_emb,
                              const float* __restrict__ item_emb) {
    int i = blockIdx.x * blockDim.x + threadIdx.x;   // float4 index
    if (i >= NV4) return;
    int node = i >> 4;
    float4 v = (node < NUM_USERS)
        ? ((const float4*)user_emb)[i]
        : ((const float4*)item_emb)[i - NUM_USERS * (EMB_DIM / 4)];
    __half2 h0 = __floats2half2_rn(v.x, v.y);
    __half2 h1 = __floats2half2_rn(v.z, v.w);
    ((__half2*)g_h0)[2 * i]     = h0;
    ((__half2*)g_h0)[2 * i + 1] = h1;
}

// ---------------------------------------------------------------------------
// CSR build: histogram -> block scan (3 kernels) -> packed scatter
// ---------------------------------------------------------------------------
__global__ void hist_kernel(const int* __restrict__ row) {
    int i = blockIdx.x * blockDim.x + threadIdx.x;
    if (i < N_EDGES) atomicAdd(&g_deg[row[i]], 1);
}

__global__ void scan1_kernel() {                     // per-block exclusive scan
    __shared__ int sm[SCAN_BLK];
    int tid = threadIdx.x;
    int i = blockIdx.x * SCAN_BLK + tid;
    int d = (i < N_NODES) ? g_deg[i] : 0;
    sm[tid] = d;
    __syncthreads();
    #pragma unroll
    for (int off = 1; off < SCAN_BLK; off <<= 1) {
        int t = (tid >= off) ? sm[tid - off] : 0;
        __syncthreads();
        sm[tid] += t;
        __syncthreads();
    }
    if (i < N_NODES) g_start[i] = sm[tid] - d;       // exclusive
    if (tid == SCAN_BLK - 1) g_bsum[blockIdx.x] = sm[tid];
}

__global__ void scan2_kernel() {                     // scan the 147 block sums
    __shared__ int sm[256];
    int tid = threadIdx.x;
    int d = (tid < SCAN_NB) ? g_bsum[tid] : 0;
    sm[tid] = d;
    __syncthreads();
    #pragma unroll
    for (int off = 1; off < 256; off <<= 1) {
        int t = (tid >= off) ? sm[tid - off] : 0;
        __syncthreads();
        sm[tid] += t;
        __syncthreads();
    }
    if (tid < SCAN_NB) g_boff[tid] = sm[tid] - d;    // exclusive
}

__global__ void scan3_kernel() {                     // add block offsets
    int i = blockIdx.x * SCAN_BLK + threadIdx.x;
    if (i < N_NODES) {
        int s = g_start[i] + g_boff[blockIdx.x];
        g_start[i] = s;
        g_fill[i]  = s;
    }
}

__global__ void scatter_kernel(const int* __restrict__ row,
                               const int* __restrict__ col,
                               const float* __restrict__ vals) {
    int i = blockIdx.x * blockDim.x + threadIdx.x;
    if (i >= N_EDGES) return;
    int p = atomicAdd(&g_fill[row[i]], 1);
    g_epack[p] = make_int2(col[i], __float_as_int(vals[i]));
}

// ---------------------------------------------------------------------------
// Pull-mode CSR SpMM, fp16 gather operand, fp32 accumulate.
//   y[r] = sum_{k in row r} val_k * xh[col_k]
// One warp per row; lane owns 2 dims (half2 load = 128 B/row coalesced).
// WRITE_HALF: also emit fp16 shadow for the next layer.
// ---------------------------------------------------------------------------
template<bool WRITE_HALF>
__global__ void __launch_bounds__(256)
spmm_csr_kernel(const __half2* __restrict__ xh,
                float* __restrict__ y,
                __half* __restrict__ yh) {
    const unsigned FULL = 0xFFFFFFFFu;
    int r    = (blockIdx.x * blockDim.x + threadIdx.x) >> 5;
    int lane = threadIdx.x & 31;
    if (r >= N_NODES) return;

    int start = g_start[r];
    int deg   = g_deg[r];

    float ax = 0.f, ay = 0.f;

    int k = 0;
    for (; k + 32 <= deg; k += 32) {
        int2 pk = g_epack[start + k + lane];
        #pragma unroll 8
        for (int j = 0; j < 32; j++) {
            int   cc = __shfl_sync(FULL, pk.x, j);
            float vv = __int_as_float(__shfl_sync(FULL, pk.y, j));
            float2 xv = __half22float2(xh[(size_t)cc * 32 + lane]);
            ax += vv * xv.x;
            ay += vv * xv.y;
        }
    }
    int n = deg - k;
    if (n > 0) {
        int2 pk = (lane < n) ? g_epack[start + k + lane] : make_int2(0, 0);
        for (int j = 0; j < n; j++) {
            int   cc = __shfl_sync(FULL, pk.x, j);
            float vv = __int_as_float(__shfl_sync(FULL, pk.y, j));
            float2 xv = __half22float2(xh[(size_t)cc * 32 + lane]);
            ax += vv * xv.x;
            ay += vv * xv.y;
        }
    }

    ((float2*)y)[(size_t)r * 32 + lane] = make_float2(ax, ay);
    if (WRITE_HALF) {
        ((__half2*)yh)[(size_t)r * 32 + lane] = __floats2half2_rn(ax, ay);
    }
}

// ---------------------------------------------------------------------------
// Masked layer-3 SpMM: rows from g_list (only scored rows, ~12K warps),
// gathers fp32 x2 directly (no fp16 shadow needed for this layer).
// ---------------------------------------------------------------------------
__global__ void __launch_bounds__(256)
spmm_csr_masked_kernel(const float* __restrict__ x,
                       float* __restrict__ y) {
    const unsigned FULL = 0xFFFFFFFFu;
    int w    = (blockIdx.x * blockDim.x + threadIdx.x) >> 5;
    int lane = threadIdx.x & 31;
    if (w >= 3 * BATCH) return;
    int r = g_list[w];

    int start = g_start[r];
    int deg   = g_deg[r];

    float ax = 0.f, ay = 0.f;

    int k = 0;
    for (; k + 32 <= deg; k += 32) {
        int2 pk = g_epack[start + k + lane];
        #pragma unroll 8
        for (int j = 0; j < 32; j++) {
            int   cc = __shfl_sync(FULL, pk.x, j);
            float vv = __int_as_float(__shfl_sync(FULL, pk.y, j));
            float2 xv = ((const float2*)x)[(size_t)cc * 32 + lane];
            ax += vv * xv.x;
            ay += vv * xv.y;
        }
    }
    int n = deg - k;
    if (n > 0) {
        int2 pk = (lane < n) ? g_epack[start + k + lane] : make_int2(0, 0);
        for (int j = 0; j < n; j++) {
            int   cc = __shfl_sync(FULL, pk.x, j);
            float vv = __int_as_float(__shfl_sync(FULL, pk.y, j));
            float2 xv = ((const float2*)x)[(size_t)cc * 32 + lane];
            ax += vv * xv.x;
            ay += vv * xv.y;
        }
    }

    ((float2*)y)[(size_t)r * 32 + lane] = make_float2(ax, ay);
}

// ---------------------------------------------------------------------------
// Scoring: one warp per batch element.
// acc = x0 + x1 + x2 + x3 (x0 from fp32 input tables); score = dot/16
// out layout: [pos_scores(4096) | neg_scores(4096)]
// ---------------------------------------------------------------------------
__global__ void score_kernel(const float* __restrict__ user_emb,
                             const float* __restrict__ item_emb,
                             const int* __restrict__ users,
                             const int* __restrict__ pos_items,
                             const int* __restrict__ neg_items,
                             float* __restrict__ out) {
    int warp = (blockIdx.x * blockDim.x + threadIdx.x) >> 5;
    int lane = threadIdx.x & 31;
    if (warp >= BATCH) return;

    int u  = users[warp];
    int pi = pos_items[warp];
    int ni = neg_items[warp];

    const float2* UE = (const float2*)user_emb;
    const float2* IE = (const float2*)item_emb;
    const float2* X1 = (const float2*)g_x1;
    const float2* X2 = (const float2*)g_x2;
    const float2* X3 = (const float2*)g_x3;

    size_t un = (size_t)u * 32 + lane;
    size_t pn = (size_t)(NUM_USERS + pi) * 32 + lane;
    size_t nn = (size_t)(NUM_USERS + ni) * 32 + lane;
    size_t pl = (size_t)pi * 32 + lane;
    size_t nl = (size_t)ni * 32 + lane;

    float2 a, t;
    a = UE[un];
    t = X1[un]; a.x += t.x; a.y += t.y;
    t = X2[un]; a.x += t.x; a.y += t.y;
    t = X3[un]; a.x += t.x; a.y += t.y;
    float2 uacc = a;
    a = IE[pl];
    t = X1[pn]; a.x += t.x; a.y += t.y;
    t = X2[pn]; a.x += t.x; a.y += t.y;
    t = X3[pn]; a.x += t.x; a.y += t.y;
    float2 pacc = a;
    a = IE[nl];
    t = X1[nn]; a.x += t.x; a.y += t.y;
    t = X2[nn]; a.x += t.x; a.y += t.y;
    t = X3[nn]; a.x += t.x; a.y += t.y;
    float2 nacc = a;

    float ps = uacc.x * pacc.x + uacc.y * pacc.y;
    float ns = uacc.x * nacc.x + uacc.y * nacc.y;
    #pragma unroll
    for (int o = 16; o > 0; o >>= 1) {
        ps += __shfl_down_sync(0xFFFFFFFFu, ps, o);
        ns += __shfl_down_sync(0xFFFFFFFFu, ns, o);
    }
    if (lane == 0) {
        out[warp]         = ps * (1.0f / 16.0f);
        out[BATCH + warp] = ns * (1.0f / 16.0f);
    }
}

// ---------------------------------------------------------------------------
extern "C" void kernel_launch(void* const* d_in, const int* in_sizes, int n_in,
                              void* d_out, int out_size) {
    const float* user_emb  = (const float*)d_in[0];
    const float* item_emb  = (const float*)d_in[1];
    const float* vals      = (const float*)d_in[2];
    const int*   row       = (const int*)d_in[3];
    const int*   col       = (const int*)d_in[4];
    const int*   users     = (const int*)d_in[5];
    const int*   pos_items = (const int*)d_in[6];
    const int*   neg_items = (const int*)d_in[7];
    float* out = (float*)d_out;

    float*  x1P; cudaGetSymbolAddress((void**)&x1P, g_x1);
    float*  x2P; cudaGetSymbolAddress((void**)&x2P, g_x2);
    float*  x3P; cudaGetSymbolAddress((void**)&x3P, g_x3);
    __half* h0P; cudaGetSymbolAddress((void**)&h0P, g_h0);
    __half* h1P; cudaGetSymbolAddress((void**)&h1P, g_h1);

    const int TB = 256;
    const int edgeBlocks     = (N_EDGES + TB - 1) / TB;
    const int rowWarpBlocks  = (N_NODES * 32 + TB - 1) / TB;    // warp per row
    const int maskWarpBlocks = (3 * BATCH * 32) / TB;           // 1536 blocks

    prep_kernel<<<(N_NODES + TB - 1) / TB, TB>>>(users, pos_items, neg_items);
    tohalf_kernel<<<(NV4 + TB - 1) / TB, TB>>>(user_emb, item_emb);

    // CSR build
    hist_kernel<<<edgeBlocks, TB>>>(row);
    scan1_kernel<<<SCAN_NB, SCAN_BLK>>>();
    scan2_kernel<<<1, 256>>>();
    scan3_kernel<<<SCAN_NB, SCAN_BLK>>>();
    scatter_kernel<<<edgeBlocks, TB>>>(row, col, vals);

    // Layer 1: h0 -> x1 (+h1)
    spmm_csr_kernel<true><<<rowWarpBlocks, TB>>>((const __half2*)h0P, x1P, h1P);
    // Layer 2: h1 -> x2 (fp32 only; layer 3 gathers fp32)
    spmm_csr_kernel<false><<<rowWarpBlocks, TB>>>((const __half2*)h1P, x2P,
                                                  nullptr);
    // Layer 3 (masked): x2 (fp32) -> x3, only rows consumed by scoring
    spmm_csr_masked_kernel<<<maskWarpBlocks, TB>>>(x2P, x3P);

    score_kernel<<<(BATCH * 32) / TB, TB>>>(user_emb, item_emb,
                                            users, pos_items, neg_items, out);
}